// round 12
// baseline (speedup 1.0000x reference)
#include <cuda_runtime.h>
#include <cuda_fp16.h>

#define N_NODES 100000
#define IN_DIM 128
#define HID 32
#define OUTD 12
#define E_CAP 3200000
#define GEMM_BLOCKS ((N_NODES + 63) / 64)   // 1563

// ---------------- scratch (device globals; zero-init at module load) -------
__device__ __align__(128) __half2 g_h1h[N_NODES * 16];  // h1 fp16, 64B rows
__device__ __align__(128) __half2 g_h2h[N_NODES * 8];   // h2 fp16 padded, 32B rows
__device__ int g_cnt[N_NODES];          // invariant: zero at entry of each call
__device__ int g_off[N_NODES];          // segment base per node
__device__ int g_cur[N_NODES];          // cursor; after scatter == base+deg
__device__ int g_total;                 // invariant: zero at entry of each call
__device__ __align__(16) int g_csr[E_CAP];

// Blackwell packed f32x2 add (ptxas won't auto-fuse; PTX only)
__device__ __forceinline__ float2 f2add(float2 a, float2 b) {
    unsigned long long ua = *(unsigned long long*)&a;
    unsigned long long ub = *(unsigned long long*)&b;
    unsigned long long uc;
    asm("add.rn.f32x2 %0, %1, %2;" : "=l"(uc) : "l"(ua), "l"(ub));
    return *(float2*)&uc;
}

// ---------------------------------------------------------------------------
// 1) degree histogram (standalone; atomic returns unused -> RED)
// ---------------------------------------------------------------------------
__global__ void k_hist(const int* __restrict__ dst, int E) {
    int t = blockIdx.x * blockDim.x + threadIdx.x;
    int base = t * 4;
    if (base + 4 <= E) {
        int4 d = *(const int4*)&dst[base];
        atomicAdd(&g_cnt[d.x], 1);
        atomicAdd(&g_cnt[d.y], 1);
        atomicAdd(&g_cnt[d.z], 1);
        atomicAdd(&g_cnt[d.w], 1);
    } else {
        for (int i = base; i < E; i++) atomicAdd(&g_cnt[dst[i]], 1);
    }
}

// ---------------------------------------------------------------------------
// 2) segment allocation via warp-aggregated atomic; rezeroes g_cnt
// ---------------------------------------------------------------------------
__global__ void __launch_bounds__(256) k_alloc() {
    int n = blockIdx.x * 256 + threadIdx.x;
    int lane = threadIdx.x & 31;
    int c = 0;
    if (n < N_NODES) {
        c = g_cnt[n];
        g_cnt[n] = 0;
    }
    int incl = c;
#pragma unroll
    for (int o = 1; o < 32; o <<= 1) {
        int v = __shfl_up_sync(0xffffffffu, incl, o);
        if (lane >= o) incl += v;
    }
    int base = 0;
    if (lane == 31) base = atomicAdd(&g_total, incl);
    base = __shfl_sync(0xffffffffu, base, 31);
    if (n < N_NODES) {
        int off = base + incl - c;
        g_off[n] = off;
        g_cur[n] = off;
    }
}

// ---------------------------------------------------------------------------
// 3) fused: GEMM1 (blocks [0, GEMM_BLOCKS)) + CSR scatter (rest).
//    GEMM is FFMA/LDS-bound; scatter is atomic-latency-bound -> they
//    overlap on complementary pipes. Scatter needs only alloc, GEMM only
//    feat/W1, and both must finish before agg1mid: perfect pairing.
// ---------------------------------------------------------------------------
__global__ void __launch_bounds__(128) k_scatter_gemm(
        const float* __restrict__ feat, const float* __restrict__ W1,
        const int* __restrict__ src, const int* __restrict__ dst, int E) {
    __shared__ float sW[IN_DIM * HID];   // 16 KB
    __shared__ float sF[64][66];

    int bid = blockIdx.x;
    int tid = threadIdx.x;

    if (bid >= GEMM_BLOCKS) {
        // ---- scatter part: 8 edges per thread, deep MLP ----
        int t = (bid - GEMM_BLOCKS) * 128 + tid;
        if (t == 0) g_total = 0;   // restore invariant (alloc already consumed it)
        int base = t * 8;
        if (base + 8 <= E) {
            int4 d0 = *(const int4*)&dst[base];
            int4 d1 = *(const int4*)&dst[base + 4];
            int4 s0 = *(const int4*)&src[base];
            int4 s1 = *(const int4*)&src[base + 4];
            int p0 = atomicAdd(&g_cur[d0.x], 1);
            int p1 = atomicAdd(&g_cur[d0.y], 1);
            int p2 = atomicAdd(&g_cur[d0.z], 1);
            int p3 = atomicAdd(&g_cur[d0.w], 1);
            int p4 = atomicAdd(&g_cur[d1.x], 1);
            int p5 = atomicAdd(&g_cur[d1.y], 1);
            int p6 = atomicAdd(&g_cur[d1.z], 1);
            int p7 = atomicAdd(&g_cur[d1.w], 1);
            g_csr[p0] = s0.x;
            g_csr[p1] = s0.y;
            g_csr[p2] = s0.z;
            g_csr[p3] = s0.w;
            g_csr[p4] = s1.x;
            g_csr[p5] = s1.y;
            g_csr[p6] = s1.z;
            g_csr[p7] = s1.w;
        } else {
            for (int i = base; i < E; i++)
                g_csr[atomicAdd(&g_cur[dst[i]], 1)] = src[i];
        }
        return;
    }

    // ---- GEMM part: h1 = feat @ W1 -> fp16 ----
    for (int i = tid; i < IN_DIM * HID; i += 128) sW[i] = W1[i];

    int nb = bid * 64;
    int warp = tid >> 5, lane = tid & 31;
    int cg = lane & 7;
    int ng = lane >> 3;
    int wrow = warp * 16 + ng * 4;

    float4 acc[4];
#pragma unroll
    for (int j = 0; j < 4; j++) acc[j] = make_float4(0.f, 0.f, 0.f, 0.f);

    for (int s = 0; s < 2; s++) {
        __syncthreads();
        for (int idx = tid; idx < 64 * 64; idx += 128) {
            int n = idx >> 6, kk = idx & 63;
            int gn = nb + n;
            sF[n][kk] = (gn < N_NODES) ? feat[gn * IN_DIM + s * 64 + kk] : 0.f;
        }
        __syncthreads();
#pragma unroll 4
        for (int kk = 0; kk < 64; kk++) {
            float4 w = *(const float4*)&sW[(s * 64 + kk) * HID + cg * 4];
#pragma unroll
            for (int j = 0; j < 4; j++) {
                float f = sF[wrow + j][kk];
                acc[j].x += f * w.x;
                acc[j].y += f * w.y;
                acc[j].z += f * w.z;
                acc[j].w += f * w.w;
            }
        }
    }

#pragma unroll
    for (int j = 0; j < 4; j++) {
        int n = nb + wrow + j;
        if (n < N_NODES) {
            __half2 pa = __floats2half2_rn(acc[j].x, acc[j].y);
            __half2 pb = __floats2half2_rn(acc[j].z, acc[j].w);
            uint2 pk;
            pk.x = *(unsigned*)&pa;
            pk.y = *(unsigned*)&pb;
            *(uint2*)&g_h1h[n * 16 + cg * 2] = pk;
        }
    }
}

// ---------------------------------------------------------------------------
// 4) agg1 + mid fused: TWO nodes per warp (16 lanes each).
// ---------------------------------------------------------------------------
__global__ void __launch_bounds__(256) k_agg1mid(const float* __restrict__ b1,
                                                 const float* __restrict__ W2) {
    __shared__ float sW2[HID * 13];   // padded stride 13 -> conflict-free
    __shared__ float sb1[HID];
    int tid = threadIdx.x;
    for (int i = tid; i < HID * OUTD; i += 256)
        sW2[(i / OUTD) * 13 + (i % OUTD)] = W2[i];
    if (tid < HID) sb1[tid] = b1[tid];
    __syncthreads();

    int warp_id = (blockIdx.x * 256 + tid) >> 5;
    int lane = tid & 31;
    int half = lane >> 4;
    int lq = lane & 15;
    int n = warp_id * 2 + half;        // N_NODES even, grid exact
    int g = lq >> 2;                   // edge slot 0..3
    int c = lq & 3;                    // 16B chunk 0..3 -> channels 8c..8c+7

    int lo = g_off[n], hi = g_cur[n];
    int deg = hi - lo;

    float2 ac0 = make_float2(0.f, 0.f);
    float2 ac1 = make_float2(0.f, 0.f);
    float2 ac2 = make_float2(0.f, 0.f);
    float2 ac3 = make_float2(0.f, 0.f);

    int i = lo;
    for (; i + 8 <= hi; i += 8) {
        int s0 = g_csr[i + g];
        int s1 = g_csr[i + 4 + g];
        uint4 q0 = *(const uint4*)&g_h1h[s0 * 16 + c * 4];
        uint4 q1 = *(const uint4*)&g_h1h[s1 * 16 + c * 4];
        __half2 h0 = __hadd2(*(__half2*)&q0.x, *(__half2*)&q1.x);
        __half2 h1 = __hadd2(*(__half2*)&q0.y, *(__half2*)&q1.y);
        __half2 h2 = __hadd2(*(__half2*)&q0.z, *(__half2*)&q1.z);
        __half2 h3 = __hadd2(*(__half2*)&q0.w, *(__half2*)&q1.w);
        ac0 = f2add(ac0, __half22float2(h0));
        ac1 = f2add(ac1, __half22float2(h1));
        ac2 = f2add(ac2, __half22float2(h2));
        ac3 = f2add(ac3, __half22float2(h3));
    }
    for (; i < hi; i += 4) {
        int e = i + g;
        bool v = e < hi;
        int s0 = g_csr[v ? e : lo];
        uint4 q0 = *(const uint4*)&g_h1h[s0 * 16 + c * 4];
        if (v) {
            ac0 = f2add(ac0, __half22float2(*(__half2*)&q0.x));
            ac1 = f2add(ac1, __half22float2(*(__half2*)&q0.y));
            ac2 = f2add(ac2, __half22float2(*(__half2*)&q0.z));
            ac3 = f2add(ac3, __half22float2(*(__half2*)&q0.w));
        }
    }

    float a[8] = {ac0.x, ac0.y, ac1.x, ac1.y, ac2.x, ac2.y, ac3.x, ac3.y};

    // reduce over 4 edge slots (bits 2..3; stays within the 16-lane half)
#pragma unroll
    for (int j = 0; j < 8; j++) {
        a[j] += __shfl_xor_sync(0xffffffffu, a[j], 4);
        a[j] += __shfl_xor_sync(0xffffffffu, a[j], 8);
    }

    // x = relu(a/deg + b1) for channels 8c..8c+7
    float inv = 1.0f / fmaxf((float)deg, 1.0f);
    float x[8];
#pragma unroll
    for (int j = 0; j < 8; j++)
        x[j] = fmaxf(a[j] * inv + sb1[c * 8 + j], 0.0f);

    // GEMV: lane computes outputs 3*g .. 3*g+2 over its 8 channels
    int jb = g * 3;
    float p0 = 0.f, p1 = 0.f, p2 = 0.f;
#pragma unroll
    for (int k = 0; k < 8; k++) {
        float xv = x[k];
        const float* w = &sW2[(c * 8 + k) * 13 + jb];
        p0 += xv * w[0];
        p1 += xv * w[1];
        p2 += xv * w[2];
    }
    // reduce over the 4 chunks (bits 0..1)
    p0 += __shfl_xor_sync(0xffffffffu, p0, 1);
    p0 += __shfl_xor_sync(0xffffffffu, p0, 2);
    p1 += __shfl_xor_sync(0xffffffffu, p1, 1);
    p1 += __shfl_xor_sync(0xffffffffu, p1, 2);
    p2 += __shfl_xor_sync(0xffffffffu, p2, 1);
    p2 += __shfl_xor_sync(0xffffffffu, p2, 2);

    // gather the 4 output triples to lq==0 of each half (width-16 shuffles)
    float o3  = __shfl_sync(0xffffffffu, p0, 4, 16);
    float o4  = __shfl_sync(0xffffffffu, p1, 4, 16);
    float o5  = __shfl_sync(0xffffffffu, p2, 4, 16);
    float o6  = __shfl_sync(0xffffffffu, p0, 8, 16);
    float o7  = __shfl_sync(0xffffffffu, p1, 8, 16);
    float o8  = __shfl_sync(0xffffffffu, p2, 8, 16);
    float o9  = __shfl_sync(0xffffffffu, p0, 12, 16);
    float o10 = __shfl_sync(0xffffffffu, p1, 12, 16);
    float o11 = __shfl_sync(0xffffffffu, p2, 12, 16);

    if (lq == 0) {
        float o[OUTD] = {p0, p1, p2, o3, o4, o5, o6, o7, o8, o9, o10, o11};
        unsigned pk[8];
#pragma unroll
        for (int j = 0; j < 6; j++) {
            __half2 h = __floats2half2_rn(o[2 * j], o[2 * j + 1]);
            pk[j] = *(unsigned*)&h;
        }
        pk[6] = 0u; pk[7] = 0u;
        uint4* hp = (uint4*)&g_h2h[n * 8];
        hp[0] = make_uint4(pk[0], pk[1], pk[2], pk[3]);
        hp[1] = make_uint4(pk[4], pk[5], pk[6], pk[7]);
    }
}

// ---------------------------------------------------------------------------
// 5) agg2: TWO nodes per warp (16 lanes each); fused /deg+b2+relu -> out
// ---------------------------------------------------------------------------
__global__ void __launch_bounds__(256) k_agg2(const float* __restrict__ b2,
                                              float* __restrict__ out) {
    int warp_id = (blockIdx.x * 256 + threadIdx.x) >> 5;
    int lane = threadIdx.x & 31;
    int half = lane >> 4;
    int lq = lane & 15;
    int n = warp_id * 2 + half;
    int g = lq >> 1;     // edge slot 0..7
    int c = lq & 1;      // chunk -> channels 8c..8c+7

    int lo = g_off[n], hi = g_cur[n];
    int deg = hi - lo;

    float2 ac0 = make_float2(0.f, 0.f);
    float2 ac1 = make_float2(0.f, 0.f);
    float2 ac2 = make_float2(0.f, 0.f);
    float2 ac3 = make_float2(0.f, 0.f);

    int i = lo;
    for (; i + 16 <= hi; i += 16) {
        int s0 = g_csr[i + g];
        int s1 = g_csr[i + 8 + g];
        uint4 q0 = *(const uint4*)&g_h2h[s0 * 8 + c * 4];
        uint4 q1 = *(const uint4*)&g_h2h[s1 * 8 + c * 4];
        __half2 h0 = __hadd2(*(__half2*)&q0.x, *(__half2*)&q1.x);
        __half2 h1 = __hadd2(*(__half2*)&q0.y, *(__half2*)&q1.y);
        __half2 h2 = __hadd2(*(__half2*)&q0.z, *(__half2*)&q1.z);
        __half2 h3 = __hadd2(*(__half2*)&q0.w, *(__half2*)&q1.w);
        ac0 = f2add(ac0, __half22float2(h0));
        ac1 = f2add(ac1, __half22float2(h1));
        ac2 = f2add(ac2, __half22float2(h2));
        ac3 = f2add(ac3, __half22float2(h3));
    }
    for (; i < hi; i += 8) {
        int e = i + g;
        bool v = e < hi;
        int s0 = g_csr[v ? e : lo];
        uint4 q0 = *(const uint4*)&g_h2h[s0 * 8 + c * 4];
        if (v) {
            ac0 = f2add(ac0, __half22float2(*(__half2*)&q0.x));
            ac1 = f2add(ac1, __half22float2(*(__half2*)&q0.y));
            ac2 = f2add(ac2, __half22float2(*(__half2*)&q0.z));
            ac3 = f2add(ac3, __half22float2(*(__half2*)&q0.w));
        }
    }

    float a[8] = {ac0.x, ac0.y, ac1.x, ac1.y, ac2.x, ac2.y, ac3.x, ac3.y};

    // reduce over 8 edge slots (bits 1..3; stays within the 16-lane half)
#pragma unroll
    for (int j = 0; j < 8; j++) {
        a[j] += __shfl_xor_sync(0xffffffffu, a[j], 2);
        a[j] += __shfl_xor_sync(0xffffffffu, a[j], 4);
        a[j] += __shfl_xor_sync(0xffffffffu, a[j], 8);
    }

    float inv = 1.0f / fmaxf((float)deg, 1.0f);
    if (lq == 0) {   // channels 0..7
        float4 r0, r1;
        r0.x = fmaxf(a[0] * inv + __ldg(&b2[0]), 0.f);
        r0.y = fmaxf(a[1] * inv + __ldg(&b2[1]), 0.f);
        r0.z = fmaxf(a[2] * inv + __ldg(&b2[2]), 0.f);
        r0.w = fmaxf(a[3] * inv + __ldg(&b2[3]), 0.f);
        r1.x = fmaxf(a[4] * inv + __ldg(&b2[4]), 0.f);
        r1.y = fmaxf(a[5] * inv + __ldg(&b2[5]), 0.f);
        r1.z = fmaxf(a[6] * inv + __ldg(&b2[6]), 0.f);
        r1.w = fmaxf(a[7] * inv + __ldg(&b2[7]), 0.f);
        *(float4*)&out[n * OUTD + 0] = r0;
        *(float4*)&out[n * OUTD + 4] = r1;
    }
    if (lq == 1) {   // channels 8..11
        float4 r;
        r.x = fmaxf(a[0] * inv + __ldg(&b2[8]), 0.f);
        r.y = fmaxf(a[1] * inv + __ldg(&b2[9]), 0.f);
        r.z = fmaxf(a[2] * inv + __ldg(&b2[10]), 0.f);
        r.w = fmaxf(a[3] * inv + __ldg(&b2[11]), 0.f);
        *(float4*)&out[n * OUTD + 8] = r;
    }
}

extern "C" void kernel_launch(void* const* d_in, const int* in_sizes, int n_in,
                              void* d_out, int out_size) {
    const float* feat = (const float*)d_in[0];
    const int* src = (const int*)d_in[1];
    const int* dst = (const int*)d_in[2];
    const float* W1 = (const float*)d_in[3];
    const float* b1 = (const float*)d_in[4];
    const float* W2 = (const float*)d_in[5];
    const float* b2 = (const float*)d_in[6];
    float* out = (float*)d_out;
    int E = in_sizes[1];
    if (E > E_CAP) E = E_CAP;

    int histBlocks = ((E + 3) / 4 + 255) / 256;
    int scatBlocks = ((E + 7) / 8 + 127) / 128;
    int aggBlocks = (N_NODES / 2 * 32) / 256;   // exact

    // #1: degree histogram
    k_hist<<<histBlocks, 256>>>(dst, E);
    // #2: segment allocation (rezeroes g_cnt)
    k_alloc<<<(N_NODES + 255) / 256, 256>>>();
    // #3: fused CSR scatter + GEMM1 (overlapping pipes; rezeroes g_total)
    k_scatter_gemm<<<GEMM_BLOCKS + scatBlocks, 128>>>(feat, W1, src, dst, E);
    // #4: agg layer 1 + mid GEMM  (profiled slot)
    k_agg1mid<<<aggBlocks, 256>>>(b1, W2);
    // #5: agg layer 2 -> out
    k_agg2<<<aggBlocks, 256>>>(b2, out);
}

// round 13
// speedup vs baseline: 1.0471x; 1.0471x over previous
#include <cuda_runtime.h>
#include <cuda_fp16.h>

#define N_NODES 100000
#define IN_DIM 128
#define HID 32
#define OUTD 12
#define E_CAP 3200000
#define GEMM_BLOCKS ((N_NODES + 63) / 64)   // 1563

// ---------------- scratch (device globals; zero-init at module load) -------
__device__ __align__(128) __half2 g_h1h[N_NODES * 16];  // h1 fp16, 64B rows
__device__ __align__(128) __half2 g_h2h[N_NODES * 8];   // h2 fp16 padded, 32B rows
__device__ int g_cnt[N_NODES];          // invariant: zero at entry of each call
__device__ int g_off[N_NODES];          // segment base per node
__device__ int g_cur[N_NODES];          // cursor; after scatter == base+deg
__device__ int g_total;                 // invariant: zero at entry of each call
__device__ __align__(16) int g_csr[E_CAP];

// Blackwell packed f32x2 add (ptxas won't auto-fuse; PTX only)
__device__ __forceinline__ float2 f2add(float2 a, float2 b) {
    unsigned long long ua = *(unsigned long long*)&a;
    unsigned long long ub = *(unsigned long long*)&b;
    unsigned long long uc;
    asm("add.rn.f32x2 %0, %1, %2;" : "=l"(uc) : "l"(ua), "l"(ub));
    return *(float2*)&uc;
}

// ---------------------------------------------------------------------------
// 1) fused: GEMM1 (blocks [0, GEMM_BLOCKS)) + degree histogram (rest)
//    -- the R11 pairing that worked; R12's scatter+gemm fusion serialized.
// ---------------------------------------------------------------------------
__global__ void __launch_bounds__(128) k_gemm_hist(
        const float* __restrict__ feat, const float* __restrict__ W1,
        const int* __restrict__ dst, int E) {
    __shared__ float sW[IN_DIM * HID];   // 16 KB
    __shared__ float sF[64][66];

    int bid = blockIdx.x;
    int tid = threadIdx.x;

    if (bid >= GEMM_BLOCKS) {
        // ---- histogram part: 8 edges per thread ----
        int t = (bid - GEMM_BLOCKS) * 128 + tid;
        int base = t * 8;
        if (base + 8 <= E) {
            int4 d0 = *(const int4*)&dst[base];
            int4 d1 = *(const int4*)&dst[base + 4];
            atomicAdd(&g_cnt[d0.x], 1);
            atomicAdd(&g_cnt[d0.y], 1);
            atomicAdd(&g_cnt[d0.z], 1);
            atomicAdd(&g_cnt[d0.w], 1);
            atomicAdd(&g_cnt[d1.x], 1);
            atomicAdd(&g_cnt[d1.y], 1);
            atomicAdd(&g_cnt[d1.z], 1);
            atomicAdd(&g_cnt[d1.w], 1);
        } else {
            for (int i = base; i < E; i++) atomicAdd(&g_cnt[dst[i]], 1);
        }
        return;
    }

    // ---- GEMM part: h1 = feat @ W1 -> fp16 ----
    for (int i = tid; i < IN_DIM * HID; i += 128) sW[i] = W1[i];

    int nb = bid * 64;
    int warp = tid >> 5, lane = tid & 31;
    int cg = lane & 7;
    int ng = lane >> 3;
    int wrow = warp * 16 + ng * 4;

    float4 acc[4];
#pragma unroll
    for (int j = 0; j < 4; j++) acc[j] = make_float4(0.f, 0.f, 0.f, 0.f);

    for (int s = 0; s < 2; s++) {
        __syncthreads();
        for (int idx = tid; idx < 64 * 64; idx += 128) {
            int n = idx >> 6, kk = idx & 63;
            int gn = nb + n;
            sF[n][kk] = (gn < N_NODES) ? feat[gn * IN_DIM + s * 64 + kk] : 0.f;
        }
        __syncthreads();
#pragma unroll 4
        for (int kk = 0; kk < 64; kk++) {
            float4 w = *(const float4*)&sW[(s * 64 + kk) * HID + cg * 4];
#pragma unroll
            for (int j = 0; j < 4; j++) {
                float f = sF[wrow + j][kk];
                acc[j].x += f * w.x;
                acc[j].y += f * w.y;
                acc[j].z += f * w.z;
                acc[j].w += f * w.w;
            }
        }
    }

#pragma unroll
    for (int j = 0; j < 4; j++) {
        int n = nb + wrow + j;
        if (n < N_NODES) {
            __half2 pa = __floats2half2_rn(acc[j].x, acc[j].y);
            __half2 pb = __floats2half2_rn(acc[j].z, acc[j].w);
            uint2 pk;
            pk.x = *(unsigned*)&pa;
            pk.y = *(unsigned*)&pb;
            *(uint2*)&g_h1h[n * 16 + cg * 2] = pk;
        }
    }
}

// ---------------------------------------------------------------------------
// 2) segment allocation via warp-aggregated atomic; rezeroes g_cnt
// ---------------------------------------------------------------------------
__global__ void __launch_bounds__(256) k_alloc() {
    int n = blockIdx.x * 256 + threadIdx.x;
    int lane = threadIdx.x & 31;
    int c = 0;
    if (n < N_NODES) {
        c = g_cnt[n];
        g_cnt[n] = 0;
    }
    int incl = c;
#pragma unroll
    for (int o = 1; o < 32; o <<= 1) {
        int v = __shfl_up_sync(0xffffffffu, incl, o);
        if (lane >= o) incl += v;
    }
    int base = 0;
    if (lane == 31) base = atomicAdd(&g_total, incl);
    base = __shfl_sync(0xffffffffu, base, 31);
    if (n < N_NODES) {
        int off = base + incl - c;
        g_off[n] = off;
        g_cur[n] = off;
    }
}

// ---------------------------------------------------------------------------
// 3) scatter edges into CSR segments, 16 edges/thread (deep MLP);
//    rezero g_total for the next call
// ---------------------------------------------------------------------------
__global__ void __launch_bounds__(256) k_scatter(const int* __restrict__ src,
                                                 const int* __restrict__ dst, int E) {
    int t = blockIdx.x * blockDim.x + threadIdx.x;
    if (t == 0) g_total = 0;
    int base = t * 16;
    if (base + 16 <= E) {
        int4 d[4], s[4];
#pragma unroll
        for (int q = 0; q < 4; q++) {
            d[q] = *(const int4*)&dst[base + q * 4];
            s[q] = *(const int4*)&src[base + q * 4];
        }
        int p[16];
#pragma unroll
        for (int q = 0; q < 4; q++) {
            p[q * 4 + 0] = atomicAdd(&g_cur[d[q].x], 1);
            p[q * 4 + 1] = atomicAdd(&g_cur[d[q].y], 1);
            p[q * 4 + 2] = atomicAdd(&g_cur[d[q].z], 1);
            p[q * 4 + 3] = atomicAdd(&g_cur[d[q].w], 1);
        }
#pragma unroll
        for (int q = 0; q < 4; q++) {
            g_csr[p[q * 4 + 0]] = s[q].x;
            g_csr[p[q * 4 + 1]] = s[q].y;
            g_csr[p[q * 4 + 2]] = s[q].z;
            g_csr[p[q * 4 + 3]] = s[q].w;
        }
    } else {
        for (int i = base; i < E; i++)
            g_csr[atomicAdd(&g_cur[dst[i]], 1)] = src[i];
    }
}

// ---------------------------------------------------------------------------
// 4) agg1 + mid fused: TWO nodes per warp (16 lanes each).
//    Main loop 16 edges/iter: 1 int4 idx load + 4 gather LDG.128 +
//    2-level HADD2 tree + packed f32x2 accumulate.
// ---------------------------------------------------------------------------
__global__ void __launch_bounds__(256) k_agg1mid(const float* __restrict__ b1,
                                                 const float* __restrict__ W2) {
    __shared__ float sW2[HID * 13];   // padded stride 13 -> conflict-free
    __shared__ float sb1[HID];
    int tid = threadIdx.x;
    for (int i = tid; i < HID * OUTD; i += 256)
        sW2[(i / OUTD) * 13 + (i % OUTD)] = W2[i];
    if (tid < HID) sb1[tid] = b1[tid];
    __syncthreads();

    int warp_id = (blockIdx.x * 256 + tid) >> 5;
    int lane = tid & 31;
    int half = lane >> 4;
    int lq = lane & 15;
    int n = warp_id * 2 + half;        // N_NODES even, grid exact
    int g = lq >> 2;                   // edge slot 0..3
    int c = lq & 3;                    // 16B chunk 0..3 -> channels 8c..8c+7

    int lo = g_off[n], hi = g_cur[n];
    int deg = hi - lo;

    float2 ac0 = make_float2(0.f, 0.f);
    float2 ac1 = make_float2(0.f, 0.f);
    float2 ac2 = make_float2(0.f, 0.f);
    float2 ac3 = make_float2(0.f, 0.f);

    // head: align i to 4 for int4 idx loads (g==0 quad processes scalars)
    int i = lo;
    int head = (lo + 3) & ~3; if (head > hi) head = hi;
    for (; i < head; i++) {
        if (g == 0) {
            uint4 q = *(const uint4*)&g_h1h[g_csr[i] * 16 + c * 4];
            ac0 = f2add(ac0, __half22float2(*(__half2*)&q.x));
            ac1 = f2add(ac1, __half22float2(*(__half2*)&q.y));
            ac2 = f2add(ac2, __half22float2(*(__half2*)&q.z));
            ac3 = f2add(ac3, __half22float2(*(__half2*)&q.w));
        }
    }
    // main: 16 edges/iter; lane handles 4 consecutive edges i+4g..i+4g+3
    for (; i + 16 <= hi; i += 16) {
        int4 ss = *(const int4*)&g_csr[i + g * 4];   // aligned: i%4==0
        uint4 q0 = *(const uint4*)&g_h1h[ss.x * 16 + c * 4];
        uint4 q1 = *(const uint4*)&g_h1h[ss.y * 16 + c * 4];
        uint4 q2 = *(const uint4*)&g_h1h[ss.z * 16 + c * 4];
        uint4 q3 = *(const uint4*)&g_h1h[ss.w * 16 + c * 4];
        __half2 t0 = __hadd2(__hadd2(*(__half2*)&q0.x, *(__half2*)&q1.x),
                             __hadd2(*(__half2*)&q2.x, *(__half2*)&q3.x));
        __half2 t1 = __hadd2(__hadd2(*(__half2*)&q0.y, *(__half2*)&q1.y),
                             __hadd2(*(__half2*)&q2.y, *(__half2*)&q3.y));
        __half2 t2 = __hadd2(__hadd2(*(__half2*)&q0.z, *(__half2*)&q1.z),
                             __hadd2(*(__half2*)&q2.z, *(__half2*)&q3.z));
        __half2 t3 = __hadd2(__hadd2(*(__half2*)&q0.w, *(__half2*)&q1.w),
                             __hadd2(*(__half2*)&q2.w, *(__half2*)&q3.w));
        ac0 = f2add(ac0, __half22float2(t0));
        ac1 = f2add(ac1, __half22float2(t1));
        ac2 = f2add(ac2, __half22float2(t2));
        ac3 = f2add(ac3, __half22float2(t3));
    }
    // tail: 4 edges/iter, guarded scalar idx
    for (; i < hi; i += 4) {
        int e = i + g;
        bool v = e < hi;
        int s0 = g_csr[v ? e : lo];
        uint4 q0 = *(const uint4*)&g_h1h[s0 * 16 + c * 4];
        if (v) {
            ac0 = f2add(ac0, __half22float2(*(__half2*)&q0.x));
            ac1 = f2add(ac1, __half22float2(*(__half2*)&q0.y));
            ac2 = f2add(ac2, __half22float2(*(__half2*)&q0.z));
            ac3 = f2add(ac3, __half22float2(*(__half2*)&q0.w));
        }
    }

    float a[8] = {ac0.x, ac0.y, ac1.x, ac1.y, ac2.x, ac2.y, ac3.x, ac3.y};

    // reduce over 4 edge slots (bits 2..3; stays within the 16-lane half)
#pragma unroll
    for (int j = 0; j < 8; j++) {
        a[j] += __shfl_xor_sync(0xffffffffu, a[j], 4);
        a[j] += __shfl_xor_sync(0xffffffffu, a[j], 8);
    }

    // x = relu(a/deg + b1) for channels 8c..8c+7
    float inv = 1.0f / fmaxf((float)deg, 1.0f);
    float x[8];
#pragma unroll
    for (int j = 0; j < 8; j++)
        x[j] = fmaxf(a[j] * inv + sb1[c * 8 + j], 0.0f);

    // GEMV: lane computes outputs 3*g .. 3*g+2 over its 8 channels
    int jb = g * 3;
    float p0 = 0.f, p1 = 0.f, p2 = 0.f;
#pragma unroll
    for (int k = 0; k < 8; k++) {
        float xv = x[k];
        const float* w = &sW2[(c * 8 + k) * 13 + jb];
        p0 += xv * w[0];
        p1 += xv * w[1];
        p2 += xv * w[2];
    }
    // reduce over the 4 chunks (bits 0..1)
    p0 += __shfl_xor_sync(0xffffffffu, p0, 1);
    p0 += __shfl_xor_sync(0xffffffffu, p0, 2);
    p1 += __shfl_xor_sync(0xffffffffu, p1, 1);
    p1 += __shfl_xor_sync(0xffffffffu, p1, 2);
    p2 += __shfl_xor_sync(0xffffffffu, p2, 1);
    p2 += __shfl_xor_sync(0xffffffffu, p2, 2);

    // gather the 4 output triples to lq==0 of each half (width-16 shuffles)
    float o3  = __shfl_sync(0xffffffffu, p0, 4, 16);
    float o4  = __shfl_sync(0xffffffffu, p1, 4, 16);
    float o5  = __shfl_sync(0xffffffffu, p2, 4, 16);
    float o6  = __shfl_sync(0xffffffffu, p0, 8, 16);
    float o7  = __shfl_sync(0xffffffffu, p1, 8, 16);
    float o8  = __shfl_sync(0xffffffffu, p2, 8, 16);
    float o9  = __shfl_sync(0xffffffffu, p0, 12, 16);
    float o10 = __shfl_sync(0xffffffffu, p1, 12, 16);
    float o11 = __shfl_sync(0xffffffffu, p2, 12, 16);

    if (lq == 0) {
        float o[OUTD] = {p0, p1, p2, o3, o4, o5, o6, o7, o8, o9, o10, o11};
        unsigned pk[8];
#pragma unroll
        for (int j = 0; j < 6; j++) {
            __half2 h = __floats2half2_rn(o[2 * j], o[2 * j + 1]);
            pk[j] = *(unsigned*)&h;
        }
        pk[6] = 0u; pk[7] = 0u;
        uint4* hp = (uint4*)&g_h2h[n * 8];
        hp[0] = make_uint4(pk[0], pk[1], pk[2], pk[3]);
        hp[1] = make_uint4(pk[4], pk[5], pk[6], pk[7]);
    }
}

// ---------------------------------------------------------------------------
// 5) agg2: TWO nodes per warp; main loop 32 edges/iter with int4 idx +
//    2-level HADD2 tree; fused /deg+b2+relu -> out
// ---------------------------------------------------------------------------
__global__ void __launch_bounds__(256) k_agg2(const float* __restrict__ b2,
                                              float* __restrict__ out) {
    int warp_id = (blockIdx.x * 256 + threadIdx.x) >> 5;
    int lane = threadIdx.x & 31;
    int half = lane >> 4;
    int lq = lane & 15;
    int n = warp_id * 2 + half;
    int g = lq >> 1;     // edge slot 0..7
    int c = lq & 1;      // chunk -> channels 8c..8c+7

    int lo = g_off[n], hi = g_cur[n];
    int deg = hi - lo;

    float2 ac0 = make_float2(0.f, 0.f);
    float2 ac1 = make_float2(0.f, 0.f);
    float2 ac2 = make_float2(0.f, 0.f);
    float2 ac3 = make_float2(0.f, 0.f);

    // head: align i to 4 (g==0 pair processes scalars)
    int i = lo;
    int head = (lo + 3) & ~3; if (head > hi) head = hi;
    for (; i < head; i++) {
        if (g == 0) {
            uint4 q = *(const uint4*)&g_h2h[g_csr[i] * 8 + c * 4];
            ac0 = f2add(ac0, __half22float2(*(__half2*)&q.x));
            ac1 = f2add(ac1, __half22float2(*(__half2*)&q.y));
            ac2 = f2add(ac2, __half22float2(*(__half2*)&q.z));
            ac3 = f2add(ac3, __half22float2(*(__half2*)&q.w));
        }
    }
    // main: 32 edges/iter; lane handles 4 consecutive edges i+4g..i+4g+3
    for (; i + 32 <= hi; i += 32) {
        int4 ss = *(const int4*)&g_csr[i + g * 4];
        uint4 q0 = *(const uint4*)&g_h2h[ss.x * 8 + c * 4];
        uint4 q1 = *(const uint4*)&g_h2h[ss.y * 8 + c * 4];
        uint4 q2 = *(const uint4*)&g_h2h[ss.z * 8 + c * 4];
        uint4 q3 = *(const uint4*)&g_h2h[ss.w * 8 + c * 4];
        __half2 t0 = __hadd2(__hadd2(*(__half2*)&q0.x, *(__half2*)&q1.x),
                             __hadd2(*(__half2*)&q2.x, *(__half2*)&q3.x));
        __half2 t1 = __hadd2(__hadd2(*(__half2*)&q0.y, *(__half2*)&q1.y),
                             __hadd2(*(__half2*)&q2.y, *(__half2*)&q3.y));
        __half2 t2 = __hadd2(__hadd2(*(__half2*)&q0.z, *(__half2*)&q1.z),
                             __hadd2(*(__half2*)&q2.z, *(__half2*)&q3.z));
        __half2 t3 = __hadd2(__hadd2(*(__half2*)&q0.w, *(__half2*)&q1.w),
                             __hadd2(*(__half2*)&q2.w, *(__half2*)&q3.w));
        ac0 = f2add(ac0, __half22float2(t0));
        ac1 = f2add(ac1, __half22float2(t1));
        ac2 = f2add(ac2, __half22float2(t2));
        ac3 = f2add(ac3, __half22float2(t3));
    }
    // tail: 8 edges/iter, guarded scalar idx
    for (; i < hi; i += 8) {
        int e = i + g;
        bool v = e < hi;
        int s0 = g_csr[v ? e : lo];
        uint4 q0 = *(const uint4*)&g_h2h[s0 * 8 + c * 4];
        if (v) {
            ac0 = f2add(ac0, __half22float2(*(__half2*)&q0.x));
            ac1 = f2add(ac1, __half22float2(*(__half2*)&q0.y));
            ac2 = f2add(ac2, __half22float2(*(__half2*)&q0.z));
            ac3 = f2add(ac3, __half22float2(*(__half2*)&q0.w));
        }
    }

    float a[8] = {ac0.x, ac0.y, ac1.x, ac1.y, ac2.x, ac2.y, ac3.x, ac3.y};

    // reduce over 8 edge slots (bits 1..3; stays within the 16-lane half)
#pragma unroll
    for (int j = 0; j < 8; j++) {
        a[j] += __shfl_xor_sync(0xffffffffu, a[j], 2);
        a[j] += __shfl_xor_sync(0xffffffffu, a[j], 4);
        a[j] += __shfl_xor_sync(0xffffffffu, a[j], 8);
    }

    float inv = 1.0f / fmaxf((float)deg, 1.0f);
    if (lq == 0) {   // channels 0..7
        float4 r0, r1;
        r0.x = fmaxf(a[0] * inv + __ldg(&b2[0]), 0.f);
        r0.y = fmaxf(a[1] * inv + __ldg(&b2[1]), 0.f);
        r0.z = fmaxf(a[2] * inv + __ldg(&b2[2]), 0.f);
        r0.w = fmaxf(a[3] * inv + __ldg(&b2[3]), 0.f);
        r1.x = fmaxf(a[4] * inv + __ldg(&b2[4]), 0.f);
        r1.y = fmaxf(a[5] * inv + __ldg(&b2[5]), 0.f);
        r1.z = fmaxf(a[6] * inv + __ldg(&b2[6]), 0.f);
        r1.w = fmaxf(a[7] * inv + __ldg(&b2[7]), 0.f);
        *(float4*)&out[n * OUTD + 0] = r0;
        *(float4*)&out[n * OUTD + 4] = r1;
    }
    if (lq == 1) {   // channels 8..11
        float4 r;
        r.x = fmaxf(a[0] * inv + __ldg(&b2[8]), 0.f);
        r.y = fmaxf(a[1] * inv + __ldg(&b2[9]), 0.f);
        r.z = fmaxf(a[2] * inv + __ldg(&b2[10]), 0.f);
        r.w = fmaxf(a[3] * inv + __ldg(&b2[11]), 0.f);
        *(float4*)&out[n * OUTD + 8] = r;
    }
}

extern "C" void kernel_launch(void* const* d_in, const int* in_sizes, int n_in,
                              void* d_out, int out_size) {
    const float* feat = (const float*)d_in[0];
    const int* src = (const int*)d_in[1];
    const int* dst = (const int*)d_in[2];
    const float* W1 = (const float*)d_in[3];
    const float* b1 = (const float*)d_in[4];
    const float* W2 = (const float*)d_in[5];
    const float* b2 = (const float*)d_in[6];
    float* out = (float*)d_out;
    int E = in_sizes[1];
    if (E > E_CAP) E = E_CAP;

    int histBlocks = ((E + 7) / 8 + 127) / 128;
    int scatBlocks = ((E + 15) / 16 + 255) / 256;
    int aggBlocks = (N_NODES / 2 * 32) / 256;   // exact

    // #1: fused gemm1 + degree histogram (R11 pairing)
    k_gemm_hist<<<GEMM_BLOCKS + histBlocks, 128>>>(feat, W1, dst, E);
    // #2: segment allocation (rezeroes g_cnt)
    k_alloc<<<(N_NODES + 255) / 256, 256>>>();
    // #3: scatter to CSR, 16 edges/thread (rezeroes g_total)
    k_scatter<<<scatBlocks, 256>>>(src, dst, E);
    // #4: agg layer 1 + mid GEMM  (profiled slot)
    k_agg1mid<<<aggBlocks, 256>>>(b1, W2);
    // #5: agg layer 2 -> out
    k_agg2<<<aggBlocks, 256>>>(b2, out);
}

// round 14
// speedup vs baseline: 1.5739x; 1.5031x over previous
#include <cuda_runtime.h>
#include <cuda_fp16.h>

#define N_NODES 100000
#define IN_DIM 128
#define HID 32
#define OUTD 12
#define E_CAP 3200000
#define GEMM_BLOCKS ((N_NODES + 63) / 64)   // 1563

// ---------------- scratch (device globals; zero-init at module load) -------
__device__ __align__(128) __half2 g_h1h[N_NODES * 16];  // h1 fp16, 64B rows
__device__ __align__(128) __half2 g_h2h[N_NODES * 8];   // h2 fp16 padded, 32B rows
__device__ int g_cnt[N_NODES];          // invariant: zero at entry of each call
__device__ int g_off[N_NODES];          // segment base per node
__device__ int g_cur[N_NODES];          // cursor; after scatter == base+deg
__device__ int g_total;                 // invariant: zero at entry of each call
__device__ __align__(16) int g_csr[E_CAP];

// Blackwell packed f32x2 add (ptxas won't auto-fuse; PTX only)
__device__ __forceinline__ float2 f2add(float2 a, float2 b) {
    unsigned long long ua = *(unsigned long long*)&a;
    unsigned long long ub = *(unsigned long long*)&b;
    unsigned long long uc;
    asm("add.rn.f32x2 %0, %1, %2;" : "=l"(uc) : "l"(ua), "l"(ub));
    return *(float2*)&uc;
}

// ---------------------------------------------------------------------------
// 1) fused: GEMM1 (blocks [0, GEMM_BLOCKS)) + degree histogram (rest)
//    (R11 pairing; 4 edges/thread hist — the measured-good config)
// ---------------------------------------------------------------------------
__global__ void __launch_bounds__(128) k_gemm_hist(
        const float* __restrict__ feat, const float* __restrict__ W1,
        const int* __restrict__ dst, int E) {
    __shared__ float sW[IN_DIM * HID];   // 16 KB
    __shared__ float sF[64][66];

    int bid = blockIdx.x;
    int tid = threadIdx.x;

    if (bid >= GEMM_BLOCKS) {
        int t = (bid - GEMM_BLOCKS) * 128 + tid;
        int base = t * 4;
        if (base + 4 <= E) {
            int4 d = *(const int4*)&dst[base];
            atomicAdd(&g_cnt[d.x], 1);
            atomicAdd(&g_cnt[d.y], 1);
            atomicAdd(&g_cnt[d.z], 1);
            atomicAdd(&g_cnt[d.w], 1);
        } else {
            for (int i = base; i < E; i++) atomicAdd(&g_cnt[dst[i]], 1);
        }
        return;
    }

    for (int i = tid; i < IN_DIM * HID; i += 128) sW[i] = W1[i];

    int nb = bid * 64;
    int warp = tid >> 5, lane = tid & 31;
    int cg = lane & 7;
    int ng = lane >> 3;
    int wrow = warp * 16 + ng * 4;

    float4 acc[4];
#pragma unroll
    for (int j = 0; j < 4; j++) acc[j] = make_float4(0.f, 0.f, 0.f, 0.f);

    for (int s = 0; s < 2; s++) {
        __syncthreads();
        for (int idx = tid; idx < 64 * 64; idx += 128) {
            int n = idx >> 6, kk = idx & 63;
            int gn = nb + n;
            sF[n][kk] = (gn < N_NODES) ? feat[gn * IN_DIM + s * 64 + kk] : 0.f;
        }
        __syncthreads();
#pragma unroll 4
        for (int kk = 0; kk < 64; kk++) {
            float4 w = *(const float4*)&sW[(s * 64 + kk) * HID + cg * 4];
#pragma unroll
            for (int j = 0; j < 4; j++) {
                float f = sF[wrow + j][kk];
                acc[j].x += f * w.x;
                acc[j].y += f * w.y;
                acc[j].z += f * w.z;
                acc[j].w += f * w.w;
            }
        }
    }

#pragma unroll
    for (int j = 0; j < 4; j++) {
        int n = nb + wrow + j;
        if (n < N_NODES) {
            __half2 pa = __floats2half2_rn(acc[j].x, acc[j].y);
            __half2 pb = __floats2half2_rn(acc[j].z, acc[j].w);
            uint2 pk;
            pk.x = *(unsigned*)&pa;
            pk.y = *(unsigned*)&pb;
            *(uint2*)&g_h1h[n * 16 + cg * 2] = pk;
        }
    }
}

// ---------------------------------------------------------------------------
// 2) segment allocation via warp-aggregated atomic; rezeroes g_cnt
// ---------------------------------------------------------------------------
__global__ void __launch_bounds__(256) k_alloc() {
    int n = blockIdx.x * 256 + threadIdx.x;
    int lane = threadIdx.x & 31;
    int c = 0;
    if (n < N_NODES) {
        c = g_cnt[n];
        g_cnt[n] = 0;
    }
    int incl = c;
#pragma unroll
    for (int o = 1; o < 32; o <<= 1) {
        int v = __shfl_up_sync(0xffffffffu, incl, o);
        if (lane >= o) incl += v;
    }
    int base = 0;
    if (lane == 31) base = atomicAdd(&g_total, incl);
    base = __shfl_sync(0xffffffffu, base, 31);
    if (n < N_NODES) {
        int off = base + incl - c;
        g_off[n] = off;
        g_cur[n] = off;
    }
}

// ---------------------------------------------------------------------------
// 3) scatter edges into CSR segments, 8 edges/thread (R11 config);
//    rezero g_total for the next call
// ---------------------------------------------------------------------------
__global__ void k_scatter(const int* __restrict__ src, const int* __restrict__ dst, int E) {
    int t = blockIdx.x * blockDim.x + threadIdx.x;
    if (t == 0) g_total = 0;
    int base = t * 8;
    if (base + 8 <= E) {
        int4 d0 = *(const int4*)&dst[base];
        int4 d1 = *(const int4*)&dst[base + 4];
        int4 s0 = *(const int4*)&src[base];
        int4 s1 = *(const int4*)&src[base + 4];
        int p0 = atomicAdd(&g_cur[d0.x], 1);
        int p1 = atomicAdd(&g_cur[d0.y], 1);
        int p2 = atomicAdd(&g_cur[d0.z], 1);
        int p3 = atomicAdd(&g_cur[d0.w], 1);
        int p4 = atomicAdd(&g_cur[d1.x], 1);
        int p5 = atomicAdd(&g_cur[d1.y], 1);
        int p6 = atomicAdd(&g_cur[d1.z], 1);
        int p7 = atomicAdd(&g_cur[d1.w], 1);
        g_csr[p0] = s0.x;
        g_csr[p1] = s0.y;
        g_csr[p2] = s0.z;
        g_csr[p3] = s0.w;
        g_csr[p4] = s1.x;
        g_csr[p5] = s1.y;
        g_csr[p6] = s1.z;
        g_csr[p7] = s1.w;
    } else {
        for (int i = base; i < E; i++)
            g_csr[atomicAdd(&g_cur[dst[i]], 1)] = src[i];
    }
}

// ---------------------------------------------------------------------------
// 4) agg1 + mid fused: TWO nodes per warp (16 lanes each). R11 structure;
//    main loop unrolled to 16 edges/iter (4 gathers in flight), scalar
//    broadcast idx loads -> NO head-alignment loop (R13's mistake).
// ---------------------------------------------------------------------------
__global__ void __launch_bounds__(256) k_agg1mid(const float* __restrict__ b1,
                                                 const float* __restrict__ W2) {
    __shared__ float sW2[HID * 13];   // padded stride 13 -> conflict-free
    __shared__ float sb1[HID];
    int tid = threadIdx.x;
    for (int i = tid; i < HID * OUTD; i += 256)
        sW2[(i / OUTD) * 13 + (i % OUTD)] = W2[i];
    if (tid < HID) sb1[tid] = b1[tid];
    __syncthreads();

    int warp_id = (blockIdx.x * 256 + tid) >> 5;
    int lane = tid & 31;
    int half = lane >> 4;
    int lq = lane & 15;
    int n = warp_id * 2 + half;        // N_NODES even, grid exact
    int g = lq >> 2;                   // edge slot 0..3
    int c = lq & 3;                    // 16B chunk 0..3 -> channels 8c..8c+7

    int lo = g_off[n], hi = g_cur[n];
    int deg = hi - lo;

    float2 ac0 = make_float2(0.f, 0.f);
    float2 ac1 = make_float2(0.f, 0.f);
    float2 ac2 = make_float2(0.f, 0.f);
    float2 ac3 = make_float2(0.f, 0.f);

    int i = lo;
    // main: 16 edges/iter, 4 independent gathers in flight per lane
    for (; i + 16 <= hi; i += 16) {
        int s0 = g_csr[i + g];
        int s1 = g_csr[i + 4 + g];
        int s2 = g_csr[i + 8 + g];
        int s3 = g_csr[i + 12 + g];
        uint4 q0 = *(const uint4*)&g_h1h[s0 * 16 + c * 4];
        uint4 q1 = *(const uint4*)&g_h1h[s1 * 16 + c * 4];
        uint4 q2 = *(const uint4*)&g_h1h[s2 * 16 + c * 4];
        uint4 q3 = *(const uint4*)&g_h1h[s3 * 16 + c * 4];
        __half2 t0 = __hadd2(__hadd2(*(__half2*)&q0.x, *(__half2*)&q1.x),
                             __hadd2(*(__half2*)&q2.x, *(__half2*)&q3.x));
        __half2 t1 = __hadd2(__hadd2(*(__half2*)&q0.y, *(__half2*)&q1.y),
                             __hadd2(*(__half2*)&q2.y, *(__half2*)&q3.y));
        __half2 t2 = __hadd2(__hadd2(*(__half2*)&q0.z, *(__half2*)&q1.z),
                             __hadd2(*(__half2*)&q2.z, *(__half2*)&q3.z));
        __half2 t3 = __hadd2(__hadd2(*(__half2*)&q0.w, *(__half2*)&q1.w),
                             __hadd2(*(__half2*)&q2.w, *(__half2*)&q3.w));
        ac0 = f2add(ac0, __half22float2(t0));
        ac1 = f2add(ac1, __half22float2(t1));
        ac2 = f2add(ac2, __half22float2(t2));
        ac3 = f2add(ac3, __half22float2(t3));
    }
    // mid tail: 8 edges (R11 body)
    if (i + 8 <= hi) {
        int s0 = g_csr[i + g];
        int s1 = g_csr[i + 4 + g];
        uint4 q0 = *(const uint4*)&g_h1h[s0 * 16 + c * 4];
        uint4 q1 = *(const uint4*)&g_h1h[s1 * 16 + c * 4];
        __half2 h0 = __hadd2(*(__half2*)&q0.x, *(__half2*)&q1.x);
        __half2 h1 = __hadd2(*(__half2*)&q0.y, *(__half2*)&q1.y);
        __half2 h2 = __hadd2(*(__half2*)&q0.z, *(__half2*)&q1.z);
        __half2 h3 = __hadd2(*(__half2*)&q0.w, *(__half2*)&q1.w);
        ac0 = f2add(ac0, __half22float2(h0));
        ac1 = f2add(ac1, __half22float2(h1));
        ac2 = f2add(ac2, __half22float2(h2));
        ac3 = f2add(ac3, __half22float2(h3));
        i += 8;
    }
    // final tail: 4 edges/iter, guarded
    for (; i < hi; i += 4) {
        int e = i + g;
        bool v = e < hi;
        int s0 = g_csr[v ? e : lo];
        uint4 q0 = *(const uint4*)&g_h1h[s0 * 16 + c * 4];
        if (v) {
            ac0 = f2add(ac0, __half22float2(*(__half2*)&q0.x));
            ac1 = f2add(ac1, __half22float2(*(__half2*)&q0.y));
            ac2 = f2add(ac2, __half22float2(*(__half2*)&q0.z));
            ac3 = f2add(ac3, __half22float2(*(__half2*)&q0.w));
        }
    }

    float a[8] = {ac0.x, ac0.y, ac1.x, ac1.y, ac2.x, ac2.y, ac3.x, ac3.y};

    // reduce over 4 edge slots (bits 2..3; stays within the 16-lane half)
#pragma unroll
    for (int j = 0; j < 8; j++) {
        a[j] += __shfl_xor_sync(0xffffffffu, a[j], 4);
        a[j] += __shfl_xor_sync(0xffffffffu, a[j], 8);
    }

    // x = relu(a/deg + b1) for channels 8c..8c+7
    float inv = 1.0f / fmaxf((float)deg, 1.0f);
    float x[8];
#pragma unroll
    for (int j = 0; j < 8; j++)
        x[j] = fmaxf(a[j] * inv + sb1[c * 8 + j], 0.0f);

    // GEMV: lane computes outputs 3*g .. 3*g+2 over its 8 channels
    int jb = g * 3;
    float p0 = 0.f, p1 = 0.f, p2 = 0.f;
#pragma unroll
    for (int k = 0; k < 8; k++) {
        float xv = x[k];
        const float* w = &sW2[(c * 8 + k) * 13 + jb];
        p0 += xv * w[0];
        p1 += xv * w[1];
        p2 += xv * w[2];
    }
    // reduce over the 4 chunks (bits 0..1)
    p0 += __shfl_xor_sync(0xffffffffu, p0, 1);
    p0 += __shfl_xor_sync(0xffffffffu, p0, 2);
    p1 += __shfl_xor_sync(0xffffffffu, p1, 1);
    p1 += __shfl_xor_sync(0xffffffffu, p1, 2);
    p2 += __shfl_xor_sync(0xffffffffu, p2, 1);
    p2 += __shfl_xor_sync(0xffffffffu, p2, 2);

    // gather the 4 output triples to lq==0 of each half (width-16 shuffles)
    float o3  = __shfl_sync(0xffffffffu, p0, 4, 16);
    float o4  = __shfl_sync(0xffffffffu, p1, 4, 16);
    float o5  = __shfl_sync(0xffffffffu, p2, 4, 16);
    float o6  = __shfl_sync(0xffffffffu, p0, 8, 16);
    float o7  = __shfl_sync(0xffffffffu, p1, 8, 16);
    float o8  = __shfl_sync(0xffffffffu, p2, 8, 16);
    float o9  = __shfl_sync(0xffffffffu, p0, 12, 16);
    float o10 = __shfl_sync(0xffffffffu, p1, 12, 16);
    float o11 = __shfl_sync(0xffffffffu, p2, 12, 16);

    if (lq == 0) {
        float o[OUTD] = {p0, p1, p2, o3, o4, o5, o6, o7, o8, o9, o10, o11};
        unsigned pk[8];
#pragma unroll
        for (int j = 0; j < 6; j++) {
            __half2 h = __floats2half2_rn(o[2 * j], o[2 * j + 1]);
            pk[j] = *(unsigned*)&h;
        }
        pk[6] = 0u; pk[7] = 0u;
        uint4* hp = (uint4*)&g_h2h[n * 8];
        hp[0] = make_uint4(pk[0], pk[1], pk[2], pk[3]);
        hp[1] = make_uint4(pk[4], pk[5], pk[6], pk[7]);
    }
}

// ---------------------------------------------------------------------------
// 5) agg2: TWO nodes per warp (16 lanes each); R11 structure with main loop
//    unrolled to 32 edges/iter (scalar broadcast idx, no alignment needed)
// ---------------------------------------------------------------------------
__global__ void __launch_bounds__(256) k_agg2(const float* __restrict__ b2,
                                              float* __restrict__ out) {
    int warp_id = (blockIdx.x * 256 + threadIdx.x) >> 5;
    int lane = threadIdx.x & 31;
    int half = lane >> 4;
    int lq = lane & 15;
    int n = warp_id * 2 + half;
    int g = lq >> 1;     // edge slot 0..7
    int c = lq & 1;      // chunk -> channels 8c..8c+7

    int lo = g_off[n], hi = g_cur[n];
    int deg = hi - lo;

    float2 ac0 = make_float2(0.f, 0.f);
    float2 ac1 = make_float2(0.f, 0.f);
    float2 ac2 = make_float2(0.f, 0.f);
    float2 ac3 = make_float2(0.f, 0.f);

    int i = lo;
    // main: 32 edges/iter, 4 independent gathers in flight per lane
    for (; i + 32 <= hi; i += 32) {
        int s0 = g_csr[i + g];
        int s1 = g_csr[i + 8 + g];
        int s2 = g_csr[i + 16 + g];
        int s3 = g_csr[i + 24 + g];
        uint4 q0 = *(const uint4*)&g_h2h[s0 * 8 + c * 4];
        uint4 q1 = *(const uint4*)&g_h2h[s1 * 8 + c * 4];
        uint4 q2 = *(const uint4*)&g_h2h[s2 * 8 + c * 4];
        uint4 q3 = *(const uint4*)&g_h2h[s3 * 8 + c * 4];
        __half2 t0 = __hadd2(__hadd2(*(__half2*)&q0.x, *(__half2*)&q1.x),
                             __hadd2(*(__half2*)&q2.x, *(__half2*)&q3.x));
        __half2 t1 = __hadd2(__hadd2(*(__half2*)&q0.y, *(__half2*)&q1.y),
                             __hadd2(*(__half2*)&q2.y, *(__half2*)&q3.y));
        __half2 t2 = __hadd2(__hadd2(*(__half2*)&q0.z, *(__half2*)&q1.z),
                             __hadd2(*(__half2*)&q2.z, *(__half2*)&q3.z));
        __half2 t3 = __hadd2(__hadd2(*(__half2*)&q0.w, *(__half2*)&q1.w),
                             __hadd2(*(__half2*)&q2.w, *(__half2*)&q3.w));
        ac0 = f2add(ac0, __half22float2(t0));
        ac1 = f2add(ac1, __half22float2(t1));
        ac2 = f2add(ac2, __half22float2(t2));
        ac3 = f2add(ac3, __half22float2(t3));
    }
    // mid tail: 16 edges (R11 body)
    if (i + 16 <= hi) {
        int s0 = g_csr[i + g];
        int s1 = g_csr[i + 8 + g];
        uint4 q0 = *(const uint4*)&g_h2h[s0 * 8 + c * 4];
        uint4 q1 = *(const uint4*)&g_h2h[s1 * 8 + c * 4];
        __half2 h0 = __hadd2(*(__half2*)&q0.x, *(__half2*)&q1.x);
        __half2 h1 = __hadd2(*(__half2*)&q0.y, *(__half2*)&q1.y);
        __half2 h2 = __hadd2(*(__half2*)&q0.z, *(__half2*)&q1.z);
        __half2 h3 = __hadd2(*(__half2*)&q0.w, *(__half2*)&q1.w);
        ac0 = f2add(ac0, __half22float2(h0));
        ac1 = f2add(ac1, __half22float2(h1));
        ac2 = f2add(ac2, __half22float2(h2));
        ac3 = f2add(ac3, __half22float2(h3));
        i += 16;
    }
    // final tail: 8 edges/iter, guarded
    for (; i < hi; i += 8) {
        int e = i + g;
        bool v = e < hi;
        int s0 = g_csr[v ? e : lo];
        uint4 q0 = *(const uint4*)&g_h2h[s0 * 8 + c * 4];
        if (v) {
            ac0 = f2add(ac0, __half22float2(*(__half2*)&q0.x));
            ac1 = f2add(ac1, __half22float2(*(__half2*)&q0.y));
            ac2 = f2add(ac2, __half22float2(*(__half2*)&q0.z));
            ac3 = f2add(ac3, __half22float2(*(__half2*)&q0.w));
        }
    }

    float a[8] = {ac0.x, ac0.y, ac1.x, ac1.y, ac2.x, ac2.y, ac3.x, ac3.y};

    // reduce over 8 edge slots (bits 1..3; stays within the 16-lane half)
#pragma unroll
    for (int j = 0; j < 8; j++) {
        a[j] += __shfl_xor_sync(0xffffffffu, a[j], 2);
        a[j] += __shfl_xor_sync(0xffffffffu, a[j], 4);
        a[j] += __shfl_xor_sync(0xffffffffu, a[j], 8);
    }

    float inv = 1.0f / fmaxf((float)deg, 1.0f);
    if (lq == 0) {   // channels 0..7
        float4 r0, r1;
        r0.x = fmaxf(a[0] * inv + __ldg(&b2[0]), 0.f);
        r0.y = fmaxf(a[1] * inv + __ldg(&b2[1]), 0.f);
        r0.z = fmaxf(a[2] * inv + __ldg(&b2[2]), 0.f);
        r0.w = fmaxf(a[3] * inv + __ldg(&b2[3]), 0.f);
        r1.x = fmaxf(a[4] * inv + __ldg(&b2[4]), 0.f);
        r1.y = fmaxf(a[5] * inv + __ldg(&b2[5]), 0.f);
        r1.z = fmaxf(a[6] * inv + __ldg(&b2[6]), 0.f);
        r1.w = fmaxf(a[7] * inv + __ldg(&b2[7]), 0.f);
        *(float4*)&out[n * OUTD + 0] = r0;
        *(float4*)&out[n * OUTD + 4] = r1;
    }
    if (lq == 1) {   // channels 8..11
        float4 r;
        r.x = fmaxf(a[0] * inv + __ldg(&b2[8]), 0.f);
        r.y = fmaxf(a[1] * inv + __ldg(&b2[9]), 0.f);
        r.z = fmaxf(a[2] * inv + __ldg(&b2[10]), 0.f);
        r.w = fmaxf(a[3] * inv + __ldg(&b2[11]), 0.f);
        *(float4*)&out[n * OUTD + 8] = r;
    }
}

extern "C" void kernel_launch(void* const* d_in, const int* in_sizes, int n_in,
                              void* d_out, int out_size) {
    const float* feat = (const float*)d_in[0];
    const int* src = (const int*)d_in[1];
    const int* dst = (const int*)d_in[2];
    const float* W1 = (const float*)d_in[3];
    const float* b1 = (const float*)d_in[4];
    const float* W2 = (const float*)d_in[5];
    const float* b2 = (const float*)d_in[6];
    float* out = (float*)d_out;
    int E = in_sizes[1];
    if (E > E_CAP) E = E_CAP;

    int histBlocks = ((E + 3) / 4 + 127) / 128;
    int scatBlocks = ((E + 7) / 8 + 255) / 256;
    int aggBlocks = (N_NODES / 2 * 32) / 256;   // exact

    // #1: fused gemm1 + degree histogram (R11 pairing)
    k_gemm_hist<<<GEMM_BLOCKS + histBlocks, 128>>>(feat, W1, dst, E);
    // #2: segment allocation (rezeroes g_cnt)
    k_alloc<<<(N_NODES + 255) / 256, 256>>>();
    // #3: scatter to CSR, 8 edges/thread (rezeroes g_total)
    k_scatter<<<scatBlocks, 256>>>(src, dst, E);
    // #4: agg layer 1 + mid GEMM  (profiled slot)
    k_agg1mid<<<aggBlocks, 256>>>(b1, W2);
    // #5: agg layer 2 -> out
    k_agg2<<<aggBlocks, 256>>>(b2, out);
}